// round 10
// baseline (speedup 1.0000x reference)
#include <cuda_runtime.h>

// FeatureShader: softmax blend + barycentric vertex-feature sampling.
// N=4, H=256, W=256, K=8, C=16; V=100000, F=200000.
// Inputs: dists(N,H,W,K) f32 | zbuf f32 | bary(N,H,W,K,3) f32 |
//         verts_features(V,C) f32 | background(C) f32 | pix_to_face i32 | faces(F,3) i32
// Output: (N,H,W,C) f32
//
// Quad design, 2 pixels per thread: 4 threads per pixel (one float4 channel
// group each), each thread processes two pixels with fully interleaved
// independent dependency chains (latency hiding via per-thread MLP).
// No shuffles, no smem, no barriers. Faces/bary/features gathered only for
// surviving weights (wk > 1e-7 * denom -> < 1e-6 rel err; measured 8e-8).

#define NPIX  (4 * 256 * 256)
#define KF    8
#define TPB   256
#define PXT   2           // pixels per thread

__global__ __launch_bounds__(TPB)
void feature_shader_kernel(const float4* __restrict__ dists4,   // (NPIX, 2 x float4)
                           const float4* __restrict__ zbuf4,    // (NPIX, 2 x float4)
                           const float*  __restrict__ bary,     // (NPIX, K, 3)
                           const float4* __restrict__ vfeat4,   // (V, 4 x float4)
                           const float4* __restrict__ bg4,      // (4 x float4)
                           const int4*   __restrict__ p2f4,     // (NPIX, 2 x int4)
                           const int*    __restrict__ faces,    // (F, 3)
                           float4*       __restrict__ out4)     // (NPIX, 4 x float4)
{
    const float INV_SIGMA = 1e4f;
    const float INV_GAMMA = 1e4f;
    const float EPSV      = 1e-10f;
    const float INV_RANGE = 1.0f / 99.0f;   // 1/(ZFAR-ZNEAR)
    const float ZFARV     = 100.0f;
    const float REL_THR   = 1e-7f;          // drop wk < REL_THR * sum(wk)

    const int  tid  = threadIdx.x;
    const int  cg   = tid & 3;                                   // channel group
    const long quad = ((long)blockIdx.x * TPB + tid) >> 2;       // pixel-pair id
    const long pixBase = quad * PXT;

    const float4 bgv = bg4[cg];

    float wk[PXT][KF];
    int   fv[PXT][KF];
    float invv[PXT], dinv[PXT], thr[PXT];

    // ---------------- Phase A: both pixels, interleaved ----------------
#pragma unroll
    for (int p = 0; p < PXT; p++) {
        const long pix = pixBase + p;
        float4 z01 = zbuf4[pix * 2 + 0];
        float4 z23 = zbuf4[pix * 2 + 1];
        float4 d01 = dists4[pix * 2 + 0];
        float4 d23 = dists4[pix * 2 + 1];
        int4   f01 = p2f4[pix * 2 + 0];
        int4   f23 = p2f4[pix * 2 + 1];

        float zv[KF] = { z01.x, z01.y, z01.z, z01.w, z23.x, z23.y, z23.z, z23.w };
        float dv[KF] = { d01.x, d01.y, d01.z, d01.w, d23.x, d23.y, d23.z, d23.w };
        fv[p][0] = f01.x; fv[p][1] = f01.y; fv[p][2] = f01.z; fv[p][3] = f01.w;
        fv[p][4] = f23.x; fv[p][5] = f23.y; fv[p][6] = f23.z; fv[p][7] = f23.w;

        float zi[KF];
        float zmax = EPSV;
#pragma unroll
        for (int k = 0; k < KF; k++) {
            float m = (fv[p][k] >= 0) ? 1.0f : 0.0f;
            float z = (ZFARV - zv[k]) * INV_RANGE * m;
            zi[k] = z;
            zmax = fmaxf(zmax, z);
            wk[p][k] = __fdividef(m, 1.0f + __expf(dv[k] * INV_SIGMA));  // prob
        }

        float dsum = 0.0f;
#pragma unroll
        for (int k = 0; k < KF; k++) {
            wk[p][k] *= __expf((zi[k] - zmax) * INV_GAMMA);
            dsum += wk[p][k];
        }

        float delta = fmaxf(__expf((EPSV - zmax) * INV_GAMMA), EPSV);
        float iv    = __fdividef(1.0f, dsum + delta);
        invv[p] = iv;
        dinv[p] = delta * iv;
        thr[p]  = dsum * REL_THR;
    }

    // ------------- Phase B: gather, interleaved across pixels -------------
    float4 acc[PXT];
#pragma unroll
    for (int p = 0; p < PXT; p++) acc[p] = make_float4(0.f, 0.f, 0.f, 0.f);

#pragma unroll
    for (int k = 0; k < KF; k++) {
#pragma unroll
        for (int p = 0; p < PXT; p++) {
            if (wk[p][k] > thr[p]) {
                const long   pix = pixBase + p;
                const int*   fr  = faces + (long)((fv[p][k] >= 0) ? fv[p][k] : 0) * 3;
                const float* bp  = bary + (pix * KF + k) * 3;
                int   v0 = fr[0], v1 = fr[1], v2 = fr[2];
                float w  = wk[p][k] * invv[p];
                float b0 = w * bp[0];
                float b1 = w * bp[1];
                float b2 = w * bp[2];
                float4 t0 = vfeat4[(long)v0 * 4 + cg];
                float4 t1 = vfeat4[(long)v1 * 4 + cg];
                float4 t2 = vfeat4[(long)v2 * 4 + cg];
                acc[p].x += b0 * t0.x + b1 * t1.x + b2 * t2.x;
                acc[p].y += b0 * t0.y + b1 * t1.y + b2 * t2.y;
                acc[p].z += b0 * t0.z + b1 * t1.z + b2 * t2.z;
                acc[p].w += b0 * t0.w + b1 * t1.w + b2 * t2.w;
            }
        }
    }

    // ---------------- Epilogue ----------------
#pragma unroll
    for (int p = 0; p < PXT; p++) {
        float4 o;
        o.x = acc[p].x + dinv[p] * bgv.x;
        o.y = acc[p].y + dinv[p] * bgv.y;
        o.z = acc[p].z + dinv[p] * bgv.z;
        o.w = acc[p].w + dinv[p] * bgv.w;
        out4[(pixBase + p) * 4 + cg] = o;
    }
}

extern "C" void kernel_launch(void* const* d_in, const int* in_sizes, int n_in,
                              void* d_out, int out_size)
{
    const float4* dists4 = (const float4*)d_in[0];
    const float4* zbuf4  = (const float4*)d_in[1];
    const float*  bary   = (const float*)d_in[2];
    const float4* vfeat4 = (const float4*)d_in[3];
    const float4* bg4    = (const float4*)d_in[4];
    const int4*   p2f4   = (const int4*)d_in[5];
    const int*    faces  = (const int*)d_in[6];
    float4*       out4   = (float4*)d_out;

    long total = (long)NPIX * 4 / PXT;     // one thread per (pixel-pair, cg)
    int  grid  = (int)(total / TPB);       // 8192 blocks
    feature_shader_kernel<<<grid, TPB>>>(dists4, zbuf4, bary, vfeat4, bg4, p2f4, faces, out4);
}

// round 14
// speedup vs baseline: 1.4122x; 1.4122x over previous
#include <cuda_runtime.h>

// FeatureShader: softmax blend + barycentric vertex-feature sampling.
// N=4, H=256, W=256, K=8, C=16; V=100000, F=200000.
// Inputs: dists(N,H,W,K) f32 | zbuf f32 | bary(N,H,W,K,3) f32 |
//         verts_features(V,C) f32 | background(C) f32 | pix_to_face i32 | faces(F,3) i32
// Output: (N,H,W,C) f32
//
// Warp-local scaffold (best measured): each 8-lane group owns one pixel.
// Phase A computes softmax weights + survivor records in registers; Phase B
// redistributes records via shuffles (no smem, no barriers) and gathers
// features only for surviving faces (wk > 1e-7 * denom; measured 8e-8 rel err).
// This round: __launch_bounds__(256,8) forces regs<=32 for full occupancy,
// plus underflow-skip on the delta exp.

#define NPIX  (4 * 256 * 256)
#define KF    8
#define PPB   32          // pixels per block
#define TPB   256         // threads per block (= PPB * KF)

__global__ __launch_bounds__(TPB, 8)
void feature_shader_kernel(const float*  __restrict__ dists,
                           const float*  __restrict__ zbuf,
                           const float*  __restrict__ bary,
                           const float2* __restrict__ vfeat2,  // (V, 8 x float2)
                           const float2* __restrict__ bg2,     // (8 x float2)
                           const int*    __restrict__ p2f,
                           const int*    __restrict__ faces,
                           float2*       __restrict__ out2)    // (NPIX, 8 x float2)
{
    const float INV_SIGMA = 1e4f;
    const float INV_GAMMA = 1e4f;
    const float EPSV      = 1e-10f;
    const float INV_RANGE = 1.0f / 99.0f;   // 1/(ZFAR-ZNEAR)
    const float ZFARV     = 100.0f;
    const float REL_THR   = 1e-7f;          // drop wk < REL_THR * denom
    const unsigned FULL   = 0xffffffffu;

    const int  tid  = threadIdx.x;
    const int  lane = tid & 31;
    const int  rel  = lane & 7;             // k within pixel / channel-pair in phase B
    const long g    = (long)blockIdx.x * (PPB * KF) + tid;   // (pix, k) flat index
    const long pix  = g >> 3;               // global pixel id of this group

    // ---------------- Phase A: per-(pixel,k) weight ----------------
    int   f  = p2f[g];
    float m  = (f >= 0) ? 1.0f : 0.0f;
    float zi = (ZFARV - zbuf[g]) * INV_RANGE * m;
    float pr = __fdividef(m, 1.0f + __expf(dists[g] * INV_SIGMA));
    float b0 = bary[g * 3 + 0];
    float b1 = bary[g * 3 + 1];
    float b2 = bary[g * 3 + 2];

    // max(z_inv) over the 8 lanes of this pixel group, clipped at EPS
    float zmax = zi;
    zmax = fmaxf(zmax, __shfl_xor_sync(FULL, zmax, 4));
    zmax = fmaxf(zmax, __shfl_xor_sync(FULL, zmax, 2));
    zmax = fmaxf(zmax, __shfl_xor_sync(FULL, zmax, 1));
    zmax = fmaxf(zmax, EPSV);

    float wk = pr * __expf((zi - zmax) * INV_GAMMA);

    // sum(wk) over group
    float dsum = wk;
    dsum += __shfl_xor_sync(FULL, dsum, 4);
    dsum += __shfl_xor_sync(FULL, dsum, 2);
    dsum += __shfl_xor_sync(FULL, dsum, 1);

    // delta: expf underflows below EPS whenever arg < -80 -> skip the MUFU
    float ed    = (EPSV - zmax) * INV_GAMMA;
    float delta = (ed > -80.0f) ? fmaxf(__expf(ed), EPSV) : EPSV;
    float inv   = __fdividef(1.0f, dsum + delta);
    float dinv  = delta * inv;

    bool keep = wk > dsum * REL_THR;     // dsum==0 -> keep false everywhere

    // survivor record (registers): premultiplied barys + vertex ids
    float w  = wk * inv;
    float r0 = w * b0, r1 = w * b1, r2 = w * b2;
    int v0 = 0, v1 = 0, v2 = 0;
    if (keep) {
        const int* fv = faces + (long)f * 3;
        v0 = fv[0]; v1 = fv[1]; v2 = fv[2];
    }

    unsigned bal  = __ballot_sync(FULL, keep);
    unsigned byte = (bal >> (lane & 24)) & 0xffu;
    int cnt = __popc(byte);

    // warp-uniform trip count = max survivors over the 4 groups in this warp
    int cntw = cnt;
    cntw = max(cntw, __shfl_xor_sync(FULL, cntw, 8));
    cntw = max(cntw, __shfl_xor_sync(FULL, cntw, 16));

    // ------------- Phase B: per-(pixel, channel-pair) gather -------------
    const int    cgh     = rel;              // channel pair 0..7
    const int    grpBase = lane & 24;
    const float2 b       = bg2[cgh];         // hoisted: overlaps gather latency
    float2 acc = make_float2(0.f, 0.f);

    for (int i = 0; i < cntw; i++) {
        unsigned srcRel = __fns(byte, 0, i + 1);   // i-th survivor lane (garbage if i>=cnt)
        unsigned src    = grpBase | (srcRel & 7);
        float w0 = __shfl_sync(FULL, r0, src);
        float w1 = __shfl_sync(FULL, r1, src);
        float w2 = __shfl_sync(FULL, r2, src);
        int   u0 = __shfl_sync(FULL, v0, src);
        int   u1 = __shfl_sync(FULL, v1, src);
        int   u2 = __shfl_sync(FULL, v2, src);
        if (i < cnt) {
            float2 f0 = vfeat2[(long)u0 * 8 + cgh];
            float2 f1 = vfeat2[(long)u1 * 8 + cgh];
            float2 f2 = vfeat2[(long)u2 * 8 + cgh];
            acc.x += w0 * f0.x + w1 * f1.x + w2 * f2.x;
            acc.y += w0 * f0.y + w1 * f1.y + w2 * f2.y;
        }
    }

    float2 o;
    o.x = acc.x + dinv * b.x;
    o.y = acc.y + dinv * b.y;
    out2[pix * 8 + cgh] = o;
}

extern "C" void kernel_launch(void* const* d_in, const int* in_sizes, int n_in,
                              void* d_out, int out_size)
{
    const float*  dists = (const float*)d_in[0];
    const float*  zbuf  = (const float*)d_in[1];
    const float*  bary  = (const float*)d_in[2];
    const float2* vfeat = (const float2*)d_in[3];
    const float2* bg2   = (const float2*)d_in[4];
    const int*    p2f   = (const int*)d_in[5];
    const int*    faces = (const int*)d_in[6];
    float2*       out2  = (float2*)d_out;

    int grid = NPIX / PPB;   // 8192 blocks
    feature_shader_kernel<<<grid, TPB>>>(dists, zbuf, bary, vfeat, bg2, p2f, faces, out2);
}

// round 16
// speedup vs baseline: 1.8775x; 1.3295x over previous
#include <cuda_runtime.h>

// FeatureShader: softmax blend + barycentric vertex-feature sampling.
// N=4, H=256, W=256, K=8, C=16; V=100000, F=200000.
// Inputs: dists(N,H,W,K) f32 | zbuf f32 | bary(N,H,W,K,3) f32 |
//         verts_features(V,C) f32 | background(C) f32 | pix_to_face i32 | faces(F,3) i32
// Output: (N,H,W,C) f32
//
// Hybrid: warp-local phase A (shuffle reductions, register records), smem
// survivor records read back with broadcast LDS in phase B (replaces the
// 6-SHFL-per-survivor redistribution). No block barriers, only __syncwarp.
// Faces/features gathered only for surviving weights
// (wk > 1e-7 * denom; measured 8e-8 rel err).

#define NPIX  (4 * 256 * 256)
#define KF    8
#define PPB   32          // pixels per block
#define TPB   256         // threads per block (= PPB * KF)

__global__ __launch_bounds__(TPB)
void feature_shader_kernel(const float*  __restrict__ dists,
                           const float*  __restrict__ zbuf,
                           const float*  __restrict__ bary,
                           const float2* __restrict__ vfeat2,  // (V, 8 x float2)
                           const float2* __restrict__ bg2,     // (8 x float2)
                           const int*    __restrict__ p2f,
                           const int*    __restrict__ faces,
                           float2*       __restrict__ out2)    // (NPIX, 8 x float2)
{
    // survivor records, compacted per local pixel (warp-private regions)
    __shared__ float4 s_recA[PPB * KF];   // {w*b0, w*b1, w*b2, bitcast v0}
    __shared__ int2   s_recB[PPB * KF];   // {v1, v2}

    const float INV_SIGMA = 1e4f;
    const float INV_GAMMA = 1e4f;
    const float EPSV      = 1e-10f;
    const float INV_RANGE = 1.0f / 99.0f;   // 1/(ZFAR-ZNEAR)
    const float ZFARV     = 100.0f;
    const float REL_THR   = 1e-7f;          // drop wk < REL_THR * denom
    const unsigned FULL   = 0xffffffffu;

    const int  tid  = threadIdx.x;
    const int  lane = tid & 31;
    const int  rel  = lane & 7;             // k within pixel / channel-pair in B
    const int  pixL = tid >> 3;             // local pixel 0..31
    const long g    = (long)blockIdx.x * (PPB * KF) + tid;   // (pix, k) flat
    const long pix  = g >> 3;               // global pixel id

    // ---------------- Phase A: per-(pixel,k) weight ----------------
    int   f  = p2f[g];
    float m  = (f >= 0) ? 1.0f : 0.0f;
    float zi = (ZFARV - zbuf[g]) * INV_RANGE * m;
    float pr = __fdividef(m, 1.0f + __expf(dists[g] * INV_SIGMA));
    float b0 = bary[g * 3 + 0];
    float b1 = bary[g * 3 + 1];
    float b2 = bary[g * 3 + 2];

    // max(z_inv) over the 8 lanes of this pixel group, clipped at EPS
    float zmax = zi;
    zmax = fmaxf(zmax, __shfl_xor_sync(FULL, zmax, 4));
    zmax = fmaxf(zmax, __shfl_xor_sync(FULL, zmax, 2));
    zmax = fmaxf(zmax, __shfl_xor_sync(FULL, zmax, 1));
    zmax = fmaxf(zmax, EPSV);

    float wk = pr * __expf((zi - zmax) * INV_GAMMA);

    // sum(wk) over group
    float dsum = wk;
    dsum += __shfl_xor_sync(FULL, dsum, 4);
    dsum += __shfl_xor_sync(FULL, dsum, 2);
    dsum += __shfl_xor_sync(FULL, dsum, 1);

    // delta: expf underflows below EPS whenever arg < -80 -> result is EPS
    float ed    = (EPSV - zmax) * INV_GAMMA;
    float delta = (ed > -80.0f) ? fmaxf(__expf(ed), EPSV) : EPSV;
    float inv   = __fdividef(1.0f, dsum + delta);
    float dinv  = delta * inv;

    bool keep = wk > dsum * REL_THR;     // dsum==0 -> keep false everywhere

    unsigned bal  = __ballot_sync(FULL, keep);
    unsigned byte = (bal >> (lane & 24)) & 0xffu;
    int cnt = __popc(byte);

    if (keep) {
        int slot = __popc(byte & ((1u << rel) - 1u));
        const int* fvp = faces + (long)f * 3;
        float w = wk * inv;
        float4 rA;
        rA.x = w * b0;
        rA.y = w * b1;
        rA.z = w * b2;
        rA.w = __int_as_float(fvp[0]);
        s_recA[pixL * KF + slot] = rA;
        s_recB[pixL * KF + slot] = make_int2(fvp[1], fvp[2]);
    }
    __syncwarp(FULL);

    // ------------- Phase B: per-(pixel, channel-pair) gather -------------
    const int    cgh = rel;                  // channel pair 0..7
    const float2 b   = bg2[cgh];             // hoisted: overlaps gather latency
    float2 acc = make_float2(0.f, 0.f);

    const float4* recA = s_recA + pixL * KF;
    const int2*   recB = s_recB + pixL * KF;

    for (int i = 0; i < cnt; i++) {
        float4 rA = recA[i];                 // group-uniform -> LDS broadcast
        int2   rB = recB[i];
        int u0 = __float_as_int(rA.w);
        float2 f0 = vfeat2[(long)u0   * 8 + cgh];
        float2 f1 = vfeat2[(long)rB.x * 8 + cgh];
        float2 f2 = vfeat2[(long)rB.y * 8 + cgh];
        acc.x += rA.x * f0.x + rA.y * f1.x + rA.z * f2.x;
        acc.y += rA.x * f0.y + rA.y * f1.y + rA.z * f2.y;
    }

    float2 o;
    o.x = acc.x + dinv * b.x;
    o.y = acc.y + dinv * b.y;
    out2[pix * 8 + cgh] = o;
}

extern "C" void kernel_launch(void* const* d_in, const int* in_sizes, int n_in,
                              void* d_out, int out_size)
{
    const float*  dists = (const float*)d_in[0];
    const float*  zbuf  = (const float*)d_in[1];
    const float*  bary  = (const float*)d_in[2];
    const float2* vfeat = (const float2*)d_in[3];
    const float2* bg2   = (const float2*)d_in[4];
    const int*    p2f   = (const int*)d_in[5];
    const int*    faces = (const int*)d_in[6];
    float2*       out2  = (float2*)d_out;

    int grid = NPIX / PPB;   // 8192 blocks
    feature_shader_kernel<<<grid, TPB>>>(dists, zbuf, bary, vfeat, bg2, p2f, faces, out2);
}

// round 17
// speedup vs baseline: 1.8967x; 1.0102x over previous
#include <cuda_runtime.h>

// FeatureShader: softmax blend + barycentric vertex-feature sampling.
// N=4, H=256, W=256, K=8, C=16; V=100000, F=200000.
// Inputs: dists(N,H,W,K) f32 | zbuf f32 | bary(N,H,W,K,3) f32 |
//         verts_features(V,C) f32 | background(C) f32 | pix_to_face i32 | faces(F,3) i32
// Output: (N,H,W,C) f32
//
// Warp-local phase A (shuffle reductions) + smem survivor records with
// broadcast LDS in phase B. Zero-default records make the first two gather
// iterations branch-free (batched 6-load MLP); bary loaded only for
// survivors; all 32-bit indexing. wk > 1e-7 * denom filter (measured 8e-8).

#define NPIX  (4 * 256 * 256)
#define KF    8
#define PPB   32          // pixels per block
#define TPB   256         // threads per block (= PPB * KF)

__global__ __launch_bounds__(TPB)
void feature_shader_kernel(const float*  __restrict__ dists,
                           const float*  __restrict__ zbuf,
                           const float*  __restrict__ bary,
                           const float2* __restrict__ vfeat2,  // (V, 8 x float2)
                           const float2* __restrict__ bg2,     // (8 x float2)
                           const int*    __restrict__ p2f,
                           const int*    __restrict__ faces,
                           float2*       __restrict__ out2)    // (NPIX, 8 x float2)
{
    __shared__ float4 s_recA[PPB * KF];   // {w*b0, w*b1, w*b2, bitcast v0}
    __shared__ int2   s_recB[PPB * KF];   // {v1, v2}

    const float INV_SIGMA = 1e4f;
    const float INV_GAMMA = 1e4f;
    const float EPSV      = 1e-10f;
    const float INV_RANGE = 1.0f / 99.0f;   // 1/(ZFAR-ZNEAR)
    const float ZFARV     = 100.0f;
    const float REL_THR   = 1e-7f;          // drop wk < REL_THR * denom
    const unsigned FULL   = 0xffffffffu;

    const int tid  = threadIdx.x;
    const int lane = tid & 31;
    const int rel  = lane & 7;              // k within pixel / channel-pair in B
    const int pixL = tid >> 3;              // local pixel 0..31
    const int g    = blockIdx.x * (PPB * KF) + tid;   // (pix,k) flat, < 2^21
    const int pix  = g >> 3;                // global pixel id

    // ---------------- Phase A: per-(pixel,k) weight ----------------
    int   f  = p2f[g];
    float m  = (f >= 0) ? 1.0f : 0.0f;
    float zi = (ZFARV - zbuf[g]) * INV_RANGE * m;
    float pr = __fdividef(m, 1.0f + __expf(dists[g] * INV_SIGMA));

    // max(z_inv) over the 8 lanes of this pixel group, clipped at EPS
    float zmax = zi;
    zmax = fmaxf(zmax, __shfl_xor_sync(FULL, zmax, 4));
    zmax = fmaxf(zmax, __shfl_xor_sync(FULL, zmax, 2));
    zmax = fmaxf(zmax, __shfl_xor_sync(FULL, zmax, 1));
    zmax = fmaxf(zmax, EPSV);

    float wk = pr * __expf((zi - zmax) * INV_GAMMA);

    // sum(wk) over group
    float dsum = wk;
    dsum += __shfl_xor_sync(FULL, dsum, 4);
    dsum += __shfl_xor_sync(FULL, dsum, 2);
    dsum += __shfl_xor_sync(FULL, dsum, 1);

    // delta: expf underflows below EPS whenever arg < -80 -> result is EPS
    float ed    = (EPSV - zmax) * INV_GAMMA;
    float delta = (ed > -80.0f) ? fmaxf(__expf(ed), EPSV) : EPSV;
    float inv   = __fdividef(1.0f, dsum + delta);
    float dinv  = delta * inv;

    bool keep = wk > dsum * REL_THR;     // dsum==0 -> keep false everywhere

    unsigned bal  = __ballot_sync(FULL, keep);
    unsigned byte = (bal >> (lane & 24)) & 0xffu;
    int cnt = __popc(byte);

    // default zero-records: w=0 (contributes exactly 0), v=0 (valid hot row)
    s_recA[pixL * KF + rel] = make_float4(0.f, 0.f, 0.f, 0.f);
    s_recB[pixL * KF + rel] = make_int2(0, 0);
    __syncwarp(FULL);

    if (keep) {
        int slot = __popc(byte & ((1u << rel) - 1u));
        const int*   fvp = faces + f * 3;
        const float* bp  = bary + g * 3;      // only survivors touch bary
        float w = wk * inv;
        float4 rA;
        rA.x = w * bp[0];
        rA.y = w * bp[1];
        rA.z = w * bp[2];
        rA.w = __int_as_float(fvp[0]);
        s_recA[pixL * KF + slot] = rA;
        s_recB[pixL * KF + slot] = make_int2(fvp[1], fvp[2]);
    }
    __syncwarp(FULL);

    // ------------- Phase B: per-(pixel, channel-pair) gather -------------
    const int    cgh = rel;                  // channel pair 0..7
    const float2 b   = bg2[cgh];
    const float4* recA = s_recA + pixL * KF;
    const int2*   recB = s_recB + pixL * KF;

    // branch-free first two records: 6 independent gathers in flight
    float4 rA0 = recA[0];
    int2   rB0 = recB[0];
    float4 rA1 = recA[1];
    int2   rB1 = recB[1];
    int u0 = __float_as_int(rA0.w);
    int u1 = __float_as_int(rA1.w);
    float2 a0 = vfeat2[u0    * 8 + cgh];
    float2 a1 = vfeat2[rB0.x * 8 + cgh];
    float2 a2 = vfeat2[rB0.y * 8 + cgh];
    float2 c0 = vfeat2[u1    * 8 + cgh];
    float2 c1 = vfeat2[rB1.x * 8 + cgh];
    float2 c2 = vfeat2[rB1.y * 8 + cgh];

    float2 acc;
    acc.x = rA0.x * a0.x + rA0.y * a1.x + rA0.z * a2.x
          + rA1.x * c0.x + rA1.y * c1.x + rA1.z * c2.x;
    acc.y = rA0.x * a0.y + rA0.y * a1.y + rA0.z * a2.y
          + rA1.x * c0.y + rA1.y * c1.y + rA1.z * c2.y;

    // rare tail (cnt >= 3)
    for (int i = 2; i < cnt; i++) {
        float4 rA = recA[i];
        int2   rB = recB[i];
        int u = __float_as_int(rA.w);
        float2 t0 = vfeat2[u    * 8 + cgh];
        float2 t1 = vfeat2[rB.x * 8 + cgh];
        float2 t2 = vfeat2[rB.y * 8 + cgh];
        acc.x += rA.x * t0.x + rA.y * t1.x + rA.z * t2.x;
        acc.y += rA.x * t0.y + rA.y * t1.y + rA.z * t2.y;
    }

    float2 o;
    o.x = acc.x + dinv * b.x;
    o.y = acc.y + dinv * b.y;
    out2[pix * 8 + cgh] = o;
}

extern "C" void kernel_launch(void* const* d_in, const int* in_sizes, int n_in,
                              void* d_out, int out_size)
{
    const float*  dists = (const float*)d_in[0];
    const float*  zbuf  = (const float*)d_in[1];
    const float*  bary  = (const float*)d_in[2];
    const float2* vfeat = (const float2*)d_in[3];
    const float2* bg2   = (const float2*)d_in[4];
    const int*    p2f   = (const int*)d_in[5];
    const int*    faces = (const int*)d_in[6];
    float2*       out2  = (float2*)d_out;

    int grid = NPIX / PPB;   // 8192 blocks
    feature_shader_kernel<<<grid, TPB>>>(dists, zbuf, bary, vfeat, bg2, p2f, faces, out2);
}